// round 6
// baseline (speedup 1.0000x reference)
#include <cuda_runtime.h>
#include <cstdint>

#define BB 4
#define NN 4096
#define CC 64
#define CEXT 72            // 64 channels + ones col (64) + 7 zero pad
#define TI 128             // i rows per block
#define TJ 32              // j per stage
#define NSPLIT 2           // j-range split across blocks
#define NST ((NN / NSPLIT) / TJ)   // 64 stages per block
#define ST 40              // smem row stride words (40 mod 32 = 8 -> conflict-free)

__device__ float g_outT[BB * CEXT * NN];   // [b][c][n] tf32; row 64 = ones
__device__ float g_sl[BB * NN];
__device__ float g_sr[BB * NN];
__device__ float g_part[NSPLIT * BB * NN * 72];  // partial D (col 64 = partial Z)

__device__ __forceinline__ unsigned tf32_bits(float x) {
    unsigned u;
    asm("cvt.rna.tf32.f32 %0, %1;" : "=r"(u) : "f"(x));
    return u;
}
__device__ __forceinline__ float ex2f(float x) {
    float r;
    asm("ex2.approx.f32 %0, %1;" : "=f"(r) : "f"(x));
    return r;
}
__device__ __forceinline__ void mma_tf32(float d[4], const unsigned a[4],
                                         unsigned b0, unsigned b1) {
    asm volatile(
        "mma.sync.aligned.m16n8k8.row.col.f32.tf32.tf32.f32 "
        "{%0,%1,%2,%3},{%4,%5,%6,%7},{%8,%9},{%0,%1,%2,%3};"
        : "+f"(d[0]), "+f"(d[1]), "+f"(d[2]), "+f"(d[3])
        : "r"(a[0]), "r"(a[1]), "r"(a[2]), "r"(a[3]), "r"(b0), "r"(b1));
}

#define BAR_SYNC(id)   asm volatile("bar.sync %0, 384;"   :: "r"(id) : "memory")
#define BAR_ARRIVE(id) asm volatile("bar.arrive %0, 384;" :: "r"(id) : "memory")

// ---------------------------------------------------------------------------
// prep (proven): out = X@W1; g_outT tf32 transposed (+ones/zero rows); sl, sr
// ---------------------------------------------------------------------------
__global__ __launch_bounds__(256) void prep_kernel(
    const float* __restrict__ X, const float* __restrict__ W1,
    const float* __restrict__ alpha)
{
    __shared__ float W1s[64 * 64];
    __shared__ float Xs[64 * 65];
    __shared__ float al[64], ar[64];

    const int tid = threadIdx.x;
    const int gr0 = blockIdx.x * 64;
    const int b0  = gr0 >> 12;
    const int n0  = gr0 & (NN - 1);

    for (int i = tid; i < 1024; i += 256)
        reinterpret_cast<float4*>(W1s)[i] = reinterpret_cast<const float4*>(W1)[i];
    for (int i = tid; i < 1024; i += 256) {
        int r = i >> 4, q = i & 15;
        float4 v = reinterpret_cast<const float4*>(X + (size_t)(gr0 + r) * CC)[q];
        Xs[r * 65 + 4 * q + 0] = v.x; Xs[r * 65 + 4 * q + 1] = v.y;
        Xs[r * 65 + 4 * q + 2] = v.z; Xs[r * 65 + 4 * q + 3] = v.w;
    }
    if (tid < 64)       al[tid]      = alpha[tid];
    else if (tid < 128) ar[tid - 64] = alpha[tid];
    __syncthreads();

    const int r  = tid >> 2;
    const int c0 = tid & 3;

    float acc[16];
#pragma unroll
    for (int q = 0; q < 16; q++) acc[q] = 0.f;
    const float4* W1v = reinterpret_cast<const float4*>(W1s);
#pragma unroll 8
    for (int k = 0; k < 64; k++) {
        float xv = Xs[r * 65 + k];
#pragma unroll
        for (int h = 0; h < 4; h++) {
            float4 wv = W1v[k * 16 + 4 * c0 + h];
            acc[4 * h + 0] += xv * wv.x;
            acc[4 * h + 1] += xv * wv.y;
            acc[4 * h + 2] += xv * wv.z;
            acc[4 * h + 3] += xv * wv.w;
        }
    }

    float vl = 0.f, vr = 0.f;
#pragma unroll
    for (int q = 0; q < 16; q++) {
        vl += acc[q] * al[16 * c0 + q];
        vr += acc[q] * ar[16 * c0 + q];
    }
    vl += __shfl_xor_sync(0xffffffffu, vl, 1);
    vl += __shfl_xor_sync(0xffffffffu, vl, 2);
    vr += __shfl_xor_sync(0xffffffffu, vr, 1);
    vr += __shfl_xor_sync(0xffffffffu, vr, 2);

    const int gr = gr0 + r;
    const int n  = gr & (NN - 1);
    if (c0 == 0) { g_sl[gr] = vl; g_sr[gr] = vr; }

    unsigned* oT = reinterpret_cast<unsigned*>(g_outT);
    size_t base = (size_t)b0 * CEXT * NN + n;
#pragma unroll
    for (int q = 0; q < 16; q++)
        oT[base + (size_t)(16 * c0 + q) * NN] = tf32_bits(acc[q]);

#pragma unroll
    for (int p = 0; p < 2; p++) {
        int it = tid + 256 * p;
        int rr = 64 + (it >> 6);
        int nn = n0 + (it & 63);
        g_outT[(size_t)b0 * CEXT * NN + (size_t)rr * NN + nn] = (rr == 64) ? 1.0f : 0.0f;
    }
}

// ---------------------------------------------------------------------------
// attn: warp-specialized tf32 mma.sync, TJ=32 stages, 3-deep pipeline,
// j-split across blockIdx.z. 384 threads: warps 0..7 consumers, 8..11 producers.
// Writes partial D (incl. Z col 64) to g_part.
// ---------------------------------------------------------------------------
#define WSZ (TI * ST)          // 5120 words
#define OSZ (CEXT * ST)        // 2880 words
#define STAGE_SZ (WSZ + OSZ)   // 8000 words
#define SMEM_BYTES (3 * STAGE_SZ * 4)   // 96000 B

template<int NT>
__device__ __forceinline__ void consume_tile(
    const float* __restrict__ wc, const float* __restrict__ oc,
    int moff, int noff, int r, int cq, float acc[2][5][4])
{
#pragma unroll
    for (int g = 0; g < 4; g++) {
        const int ko = g * 8 + 2 * cq;
        unsigned a[2][4];
#pragma unroll
        for (int mt = 0; mt < 2; mt++) {
            int rr = moff + mt * 16 + r;
            float2 v0 = *reinterpret_cast<const float2*>(wc + rr * ST + ko);
            float2 v1 = *reinterpret_cast<const float2*>(wc + (rr + 8) * ST + ko);
            a[mt][0] = __float_as_uint(v0.x);
            a[mt][1] = __float_as_uint(v1.x);
            a[mt][2] = __float_as_uint(v0.y);
            a[mt][3] = __float_as_uint(v1.y);
        }
#pragma unroll
        for (int nt = 0; nt < NT; nt++) {
            int nn = noff + nt * 8 + r;
            float2 bv = *reinterpret_cast<const float2*>(oc + nn * ST + ko);
            unsigned b0 = __float_as_uint(bv.x);
            unsigned b1 = __float_as_uint(bv.y);
            mma_tf32(acc[0][nt], a[0], b0, b1);
            mma_tf32(acc[1][nt], a[1], b0, b1);
        }
    }
}

__global__ void __launch_bounds__(384, 2) attn_kernel(const float* __restrict__ A_)
{
    extern __shared__ float sm[];

    const int b      = blockIdx.y;
    const int i_base = blockIdx.x * TI;
    const int split  = blockIdx.z;
    const int jb0    = split * (NN / NSPLIT);
    const int tid    = threadIdx.x;

    if (tid < 256) {
        // ---------------- consumers ----------------
        const int lane = tid & 31, wid = tid >> 5;
        const int wm = wid & 3, wn = wid >> 2;
        const int r = lane >> 2, cq = lane & 3;
        const int moff = wm * 32, noff = wn * 40;

        float acc[2][5][4];
#pragma unroll
        for (int mt = 0; mt < 2; mt++)
#pragma unroll
            for (int nt = 0; nt < 5; nt++)
#pragma unroll
                for (int e = 0; e < 4; e++) acc[mt][nt][e] = 0.f;

        int buf = 0;
        for (int s = 0; s < NST; s++) {
            BAR_SYNC(1 + buf);
            const float* wc = sm + buf * STAGE_SZ;
            const float* oc = wc + WSZ;
            if (wn == 0) consume_tile<5>(wc, oc, moff, noff, r, cq, acc);
            else         consume_tile<4>(wc, oc, moff, noff, r, cq, acc);
            BAR_ARRIVE(4 + buf);
            buf = (buf == 2) ? 0 : buf + 1;
        }

        // write partial D (raw, incl. Z col 64 for wn==1 nt==3)
        float* pb = g_part + ((size_t)(split * BB + b) * NN + i_base) * 72;
        const int ntmax = (wn == 0) ? 5 : 4;
#pragma unroll
        for (int mt = 0; mt < 2; mt++) {
            int rr = moff + mt * 16 + r;
#pragma unroll
            for (int nt = 0; nt < 5; nt++) {
                if (nt >= ntmax) break;
                int col = noff + nt * 8 + 2 * cq;
                *reinterpret_cast<float2*>(pb + (size_t)rr * 72 + col) =
                    make_float2(acc[mt][nt][0], acc[mt][nt][1]);
                *reinterpret_cast<float2*>(pb + (size_t)(rr + 8) * 72 + col) =
                    make_float2(acc[mt][nt][2], acc[mt][nt][3]);
            }
        }
    } else {
        // ---------------- producers (4 warps, 128 threads) ----------------
        const int ptid = tid - 256;      // 0..127
        const int jj   = ptid & 7;       // j cols 4*jj..+3 within stage
        const int rgrp = ptid >> 3;      // rows rgrp + 16k, k<8
        const int j0   = 4 * jj;

        const float* Abase = A_ + (size_t)(i_base + rgrp) * NN + jb0 + j0;
        const float* oTb   = g_outT + (size_t)b * CEXT * NN + jb0;
        const float* srb   = g_sr + b * NN + jb0 + j0;

        float cl[8];
        unsigned fl[8];
#pragma unroll
        for (int k = 0; k < 8; k++) {
            float s_ = g_sl[b * NN + i_base + rgrp + 16 * k];
            fl[k] = (s_ > 0.f);
            cl[k] = fabsf(s_) * 1.44269504f;   // |sl| * log2(e)
        }

        int osrc[5], odst[5];
#pragma unroll
        for (int p = 0; p < 5; p++) {
            int it = ptid + 128 * p;     // 0..639; valid < 576
            int rr = it >> 3, q = it & 7;
            osrc[p] = rr * NN + 4 * q;
            odst[p] = rr * (ST / 4) + q;  // float4 index
        }
        const bool ov4 = (ptid < 64);

        float4 a4[8], o4[5], sr4;

        auto preload = [&](int s) {
            const int jb = s * TJ;
#pragma unroll
            for (int k = 0; k < 8; k++)
                a4[k] = *reinterpret_cast<const float4*>(Abase + (size_t)(16 * k) * NN + jb);
            sr4 = *reinterpret_cast<const float4*>(srb + jb);
#pragma unroll
            for (int p = 0; p < 4; p++)
                o4[p] = *reinterpret_cast<const float4*>(oTb + osrc[p] + jb);
            if (ov4)
                o4[4] = *reinterpret_cast<const float4*>(oTb + osrc[4] + jb);
        };
        auto commit = [&](int s, float* wbuf, float* obuf) {
            const int jst = jb0 + s * TJ;        // global j of stage start
            // diagonal fixup: only stages overlapping [i_base, i_base+TI)
            if (jst >= i_base && jst < i_base + TI) {
#pragma unroll
                for (int k = 0; k < 8; k++) {
                    int d = (i_base + rgrp + 16 * k) - jst;
                    if ((unsigned)d < (unsigned)TJ && (d >> 2) == jj)
                        reinterpret_cast<float*>(&a4[k])[d & 3] = 1.0f;
                }
            }
            float lp[4], lm[4];
            const float* srv = reinterpret_cast<const float*>(&sr4);
#pragma unroll
            for (int e = 0; e < 4; e++) {
                lp[e] = fmaxf(srv[e], 0.01f * srv[e]);
                lm[e] = fmaxf(-srv[e], -0.01f * srv[e]);
            }
            uint4* wu = reinterpret_cast<uint4*>(wbuf);
#pragma unroll
            for (int k = 0; k < 8; k++) {
                const float* av = reinterpret_cast<const float*>(&a4[k]);
                int row = rgrp + 16 * k;
                uint4 wv;
                float t0 = cl[k] * (fl[k] ? lp[0] : lm[0]);
                float t1 = cl[k] * (fl[k] ? lp[1] : lm[1]);
                float t2 = cl[k] * (fl[k] ? lp[2] : lm[2]);
                float t3 = cl[k] * (fl[k] ? lp[3] : lm[3]);
                wv.x = tf32_bits(ex2f(t0) * av[0]);
                wv.y = tf32_bits(ex2f(t1) * av[1]);
                wv.z = tf32_bits(ex2f(t2) * av[2]);
                wv.w = tf32_bits(ex2f(t3) * av[3]);
                wu[row * (ST / 4) + jj] = wv;
            }
            float4* ou = reinterpret_cast<float4*>(obuf);
#pragma unroll
            for (int p = 0; p < 4; p++) ou[odst[p]] = o4[p];
            if (ov4) ou[odst[4]] = o4[4];
        };

        int buf = 0;
        preload(0);
        for (int s = 0; s < NST; s++) {
            if (s >= 3) BAR_SYNC(4 + buf);
            commit(s, sm + buf * STAGE_SZ, sm + buf * STAGE_SZ + WSZ);
            BAR_ARRIVE(1 + buf);
            if (s + 1 < NST) preload(s + 1);
            buf = (buf == 2) ? 0 : buf + 1;
        }
    }
}

// ---------------------------------------------------------------------------
// combine: agg = (part0 + part1), Z = sum col 64; out = (agg @ W2) / Z
// block = 64 rows, 256 threads
// ---------------------------------------------------------------------------
__global__ __launch_bounds__(256) void combine_kernel(
    const float* __restrict__ W2, float* __restrict__ out)
{
    __shared__ float aggS[64 * 68];
    __shared__ float W2s[64 * 64];
    __shared__ float invZ[64];

    const int tid = threadIdx.x;
    const int gr0 = blockIdx.x * 64;
    const int b   = gr0 >> 12;
    const int i0  = gr0 & (NN - 1);

    for (int i = tid; i < 1024; i += 256)
        reinterpret_cast<float4*>(W2s)[i] = reinterpret_cast<const float4*>(W2)[i];

    const float* p0 = g_part + ((size_t)b * NN + i0) * 72;
    const float* p1 = p0 + (size_t)BB * NN * 72;

    for (int idx = tid; idx < 1024; idx += 256) {
        int r = idx >> 4, q = idx & 15;
        float4 u = *reinterpret_cast<const float4*>(p0 + (size_t)r * 72 + 4 * q);
        float4 v = *reinterpret_cast<const float4*>(p1 + (size_t)r * 72 + 4 * q);
        aggS[r * 68 + 4 * q + 0] = u.x + v.x;
        aggS[r * 68 + 4 * q + 1] = u.y + v.y;
        aggS[r * 68 + 4 * q + 2] = u.z + v.z;
        aggS[r * 68 + 4 * q + 3] = u.w + v.w;
    }
    if (tid < 64)
        invZ[tid] = 1.0f / (p0[(size_t)tid * 72 + 64] + p1[(size_t)tid * 72 + 64]);
    __syncthreads();

    const int r0 = tid >> 2;
    const int c0 = tid & 3;
    float res[16];
#pragma unroll
    for (int q = 0; q < 16; q++) res[q] = 0.f;
#pragma unroll 8
    for (int k = 0; k < 64; k++) {
        float a0 = aggS[r0 * 68 + k];
#pragma unroll
        for (int q = 0; q < 16; q++)
            res[q] += a0 * W2s[k * 64 + c0 + 4 * q];
    }
    float iz = invZ[r0];
    float* ob = out + ((size_t)b * NN + i0 + r0) * CC;
#pragma unroll
    for (int q = 0; q < 16; q++)
        ob[c0 + 4 * q] = res[q] * iz;
}

// ---------------------------------------------------------------------------
extern "C" void kernel_launch(void* const* d_in, const int* in_sizes, int n_in,
                              void* d_out, int out_size)
{
    (void)in_sizes; (void)n_in; (void)out_size;
    const float* X  = (const float*)d_in[0];
    const float* A_ = (const float*)d_in[1];
    const float* W1 = (const float*)d_in[2];
    const float* W2 = (const float*)d_in[3];
    const float* al = (const float*)d_in[4];
    float* out = (float*)d_out;

    cudaFuncSetAttribute(attn_kernel, cudaFuncAttributeMaxDynamicSharedMemorySize,
                         SMEM_BYTES);

    prep_kernel<<<BB * NN / 64, 256>>>(X, W1, al);

    dim3 grid(NN / TI, BB, NSPLIT);
    attn_kernel<<<grid, 384, SMEM_BYTES>>>(A_);

    combine_kernel<<<BB * NN / 64, 256>>>(W2, out);
}